// round 8
// baseline (speedup 1.0000x reference)
#include <cuda_runtime.h>
#include <math_constants.h>
#include <cfloat>

#define NN 8192
#define DD 128
#define TOPK 32

// Per-feature top-K values and row indices, layout [d][k] (R1-proven).
__device__ __align__(16) float g_topv[DD * TOPK];
__device__ __align__(16) int   g_topi[DD * TOPK];

// ---------------------------------------------------------------------------
// Kernel 1: per-feature top-K selection (R1-proven version, verbatim).
// ---------------------------------------------------------------------------
__global__ __launch_bounds__(1024) void topk_kernel(const float* __restrict__ x) {
    const int d   = blockIdx.x;
    const int tid = threadIdx.x;

    float v[8];
#pragma unroll
    for (int j = 0; j < 8; j++)
        v[j] = x[(size_t)(j * 1024 + tid) * DD + d];

    __shared__ float s_wv[32];
    __shared__ int   s_wi[32];
    __shared__ int   s_bi;

    for (int k = 0; k < TOPK; k++) {
        float bv = v[0]; int bj = 0;
#pragma unroll
        for (int j = 1; j < 8; j++)
            if (v[j] > bv) { bv = v[j]; bj = j; }
        int bi = bj * 1024 + tid;

#pragma unroll
        for (int o = 16; o > 0; o >>= 1) {
            float ov = __shfl_down_sync(0xffffffffu, bv, o);
            int   oi = __shfl_down_sync(0xffffffffu, bi, o);
            if (ov > bv) { bv = ov; bi = oi; }
        }
        if ((tid & 31) == 0) { s_wv[tid >> 5] = bv; s_wi[tid >> 5] = bi; }
        __syncthreads();

        if (tid < 32) {
            bv = s_wv[tid]; bi = s_wi[tid];
#pragma unroll
            for (int o = 16; o > 0; o >>= 1) {
                float ov = __shfl_down_sync(0xffffffffu, bv, o);
                int   oi = __shfl_down_sync(0xffffffffu, bi, o);
                if (ov > bv) { bv = ov; bi = oi; }
            }
            if (tid == 0) {
                s_bi = bi;
                g_topv[d * TOPK + k] = bv;
                g_topi[d * TOPK + k] = bi;
            }
        }
        __syncthreads();

        int wi = s_bi;
        if ((wi & 1023) == tid) v[wi >> 10] = -CUDART_INF_F;
    }
}

// ---------------------------------------------------------------------------
// Kernel 2: probe with PAIRED SPECULATION. One warp per row; lane owns 4
// features (d = f*32+lane). Each trip issues candidates k and k+1 for every
// live feature -> 8 independent loads/lane at ~32-40 regs (occupancy kept).
// smem tables staged transposed to [k][d]: LDS bank = lane, conflict-free.
// TOPK even => k+1 <= 31 always valid. Exact fallback unchanged.
// ---------------------------------------------------------------------------
__global__ __launch_bounds__(256, 6) void probe_kernel(const float* __restrict__ x,
                                                       const int*   __restrict__ adj,
                                                       float*       __restrict__ out) {
    __shared__ float s_topv[TOPK * DD];   // [k*DD + d]
    __shared__ int   s_topi[TOPK * DD];
    for (int t = threadIdx.x; t < TOPK * DD; t += blockDim.x) {
        int k = t >> 7;          // t / DD
        int d = t & (DD - 1);    // t % DD
        s_topv[t] = g_topv[d * TOPK + k];
        s_topi[t] = g_topi[d * TOPK + k];
    }
    __syncthreads();

    const int warp = threadIdx.x >> 5;
    const int lane = threadIdx.x & 31;
    const int row  = blockIdx.x * 8 + warp;
    const int* __restrict__ arow = adj + (size_t)row * NN;

    int doff[4];
#pragma unroll
    for (int f = 0; f < 4; f++) doff[f] = f * 32 + lane;

    int      k[4]  = {0, 0, 0, 0};
    float    res[4];
    unsigned done = 0;
    unsigned fb   = 0;

#pragma unroll 1
    while (done != 0xFu) {
        int c0[4], c1[4], a0[4], a1[4];
        // candidate columns k and k+1 (conflict-free LDS)
#pragma unroll
        for (int f = 0; f < 4; f++)
            if (!((done >> f) & 1)) {
                c0[f] = s_topi[k[f] * DD + doff[f]];
                c1[f] = s_topi[(k[f] + 1) * DD + doff[f]];
            }
        // up to 8 independent probes in flight
#pragma unroll
        for (int f = 0; f < 4; f++)
            if (!((done >> f) & 1)) {
                a0[f] = __ldcg(arow + c0[f]);
                a1[f] = __ldcg(arow + c1[f]);
            }
        // resolve: first hit in rank order
#pragma unroll
        for (int f = 0; f < 4; f++) {
            if (!((done >> f) & 1)) {
                if (a0[f] != 0) {
                    res[f] = s_topv[k[f] * DD + doff[f]];
                    done |= 1u << f;
                } else if (a1[f] != 0) {
                    res[f] = s_topv[(k[f] + 1) * DD + doff[f]];
                    done |= 1u << f;
                } else {
                    k[f] += 2;
                    if (k[f] == TOPK) {
                        fb   |= 1u << f;   // exact fallback (~never: p=2^-32)
                        done |= 1u << f;
                    }
                }
            }
        }
    }

    if (fb) {  // exact fallback: full masked row scan (also no-neighbor -> 0)
#pragma unroll 1
        for (int f = 0; f < 4; f++) {
            if ((fb >> f) & 1) {
                const int d = doff[f];
                float m = -FLT_MAX; int any = 0;
                for (int j = 0; j < NN; j++) {
                    if (arow[j] != 0) { any = 1; m = fmaxf(m, x[(size_t)j * DD + d]); }
                }
                res[f] = any ? m : 0.0f;
            }
        }
    }

#pragma unroll
    for (int f = 0; f < 4; f++)
        out[(size_t)row * DD + doff[f]] = res[f];
}

extern "C" void kernel_launch(void* const* d_in, const int* in_sizes, int n_in,
                              void* d_out, int out_size) {
    const float* x   = (const float*)d_in[0];
    const int*   adj = (const int*)d_in[1];
    float*       out = (float*)d_out;

    topk_kernel<<<DD, 1024>>>(x);
    probe_kernel<<<NN / 8, 256>>>(x, adj, out);
}

// round 10
// speedup vs baseline: 2.1601x; 2.1601x over previous
#include <cuda_runtime.h>
#include <math_constants.h>
#include <cfloat>

#define NN 8192
#define DD 128
#define TOPK 32

// Per-feature top-K, TRANSPOSED layout: g_topv[k*DD + d] = k-th largest of feature d.
__device__ __align__(16) float g_topv[TOPK * DD];
__device__ __align__(16) int   g_topi[TOPK * DD];

// float -> order-preserving uint32 (bijective; larger float => larger uint)
__device__ __forceinline__ unsigned f2ord(float f) {
    unsigned b = __float_as_uint(f);
    return (b & 0x80000000u) ? ~b : (b | 0x80000000u);
}
__device__ __forceinline__ float ord2f(unsigned u) {
    unsigned b = (u & 0x80000000u) ? (u ^ 0x80000000u) : ~u;
    return __uint_as_float(b);
}

// ---------------------------------------------------------------------------
// Kernel 1: per-feature top-K selection. R1's proven structure (block argmax
// x32 with s_bi broadcast + owner-clear), but warp reductions use REDUX
// (__reduce_max_sync) + ballot/ffs instead of 5-level shuffle ladders.
// One CTA (1024 threads) per feature d; thread holds 8 rows in registers.
// ---------------------------------------------------------------------------
__global__ __launch_bounds__(1024) void topk_kernel(const float* __restrict__ x) {
    const int d    = blockIdx.x;
    const int tid  = threadIdx.x;
    const int w    = tid >> 5;
    const int lane = tid & 31;

    unsigned v[8];
#pragma unroll
    for (int j = 0; j < 8; j++)
        v[j] = f2ord(x[(size_t)(j * 1024 + tid) * DD + d]);

    __shared__ unsigned s_wv[32];
    __shared__ int      s_wi[32];
    __shared__ int      s_bi;

    for (int k = 0; k < TOPK; k++) {
        // thread-local argmax over 8 register slots
        unsigned bk = v[0]; int bj = 0;
#pragma unroll
        for (int j = 1; j < 8; j++)
            if (v[j] > bk) { bk = v[j]; bj = j; }
        int bi = bj * 1024 + tid;  // global row index (row = j*1024 + tid)

        // warp argmax via REDUX + ballot (deterministic: lowest lane wins ties)
        unsigned wm   = __reduce_max_sync(0xffffffffu, bk);
        unsigned ball = __ballot_sync(0xffffffffu, bk == wm);
        int      src  = __ffs(ball) - 1;
        int      wbi  = __shfl_sync(0xffffffffu, bi, src);
        if (lane == 0) { s_wv[w] = wm; s_wi[w] = wbi; }
        __syncthreads();

        if (tid < 32) {
            unsigned k2 = s_wv[tid];
            int      i2 = s_wi[tid];
            unsigned wm2   = __reduce_max_sync(0xffffffffu, k2);
            unsigned ball2 = __ballot_sync(0xffffffffu, k2 == wm2);
            int      src2  = __ffs(ball2) - 1;
            int      wbi2  = __shfl_sync(0xffffffffu, i2, src2);
            if (tid == 0) {
                s_bi = wbi2;
                g_topv[k * DD + d] = ord2f(wm2);  // transposed layout
                g_topi[k * DD + d] = wbi2;
            }
        }
        __syncthreads();

        // owner of the winning row clears its register slot (rows unique)
        int wi = s_bi;
        if ((wi & 1023) == tid) v[wi >> 10] = 0u;  // 0 < f2ord of any finite float
    }
}

// ---------------------------------------------------------------------------
// Kernel 2: probe (R3-proven body, verbatim). One warp per row; lane owns 4
// features (d = f*32+lane), advanced INTERLEAVED (MLP=4; probe k issued only
// after k-1 missed -> minimal DRAM bytes). Tables are [k][d] in gmem, so
// staging is float4-coalesced and LDS is bank-conflict-free (bank = lane).
// ---------------------------------------------------------------------------
__global__ __launch_bounds__(512) void probe_kernel(const float* __restrict__ x,
                                                    const int*   __restrict__ adj,
                                                    float*       __restrict__ out) {
    __shared__ __align__(16) float s_topv[TOPK * DD];
    __shared__ __align__(16) int   s_topi[TOPK * DD];
    {
        const float4* gv = (const float4*)g_topv;
        const int4*   gi = (const int4*)g_topi;
        float4* sv = (float4*)s_topv;
        int4*   si = (int4*)s_topi;
        for (int t = threadIdx.x; t < TOPK * DD / 4; t += blockDim.x) {
            sv[t] = gv[t];
            si[t] = gi[t];
        }
    }
    __syncthreads();

    const int warp = threadIdx.x >> 5;
    const int lane = threadIdx.x & 31;
    const int row  = blockIdx.x * 16 + warp;
    const int* __restrict__ arow = adj + (size_t)row * NN;

    int doff[4];
#pragma unroll
    for (int f = 0; f < 4; f++) doff[f] = f * 32 + lane;

    int      k[4]  = {0, 0, 0, 0};
    float    res[4];
    unsigned done = 0;
    unsigned fb   = 0;

#pragma unroll 1
    while (done != 0xFu) {
        int cc[4], a[4];
#pragma unroll
        for (int f = 0; f < 4; f++)
            if (!((done >> f) & 1))
                cc[f] = s_topi[k[f] * DD + doff[f]];
#pragma unroll
        for (int f = 0; f < 4; f++)
            if (!((done >> f) & 1))
                a[f] = arow[cc[f]];
#pragma unroll
        for (int f = 0; f < 4; f++) {
            if (!((done >> f) & 1)) {
                if (a[f] != 0) {
                    res[f] = s_topv[k[f] * DD + doff[f]];
                    done |= 1u << f;
                } else if (++k[f] == TOPK) {
                    fb   |= 1u << f;      // exact fallback (~never: p=2^-32)
                    done |= 1u << f;
                }
            }
        }
    }

    if (fb) {  // exact fallback: full masked row scan (also no-neighbor -> 0)
#pragma unroll 1
        for (int f = 0; f < 4; f++) {
            if ((fb >> f) & 1) {
                const int d = doff[f];
                float m = -FLT_MAX; int any = 0;
                for (int j = 0; j < NN; j++) {
                    if (arow[j] != 0) { any = 1; m = fmaxf(m, x[(size_t)j * DD + d]); }
                }
                res[f] = any ? m : 0.0f;
            }
        }
    }

#pragma unroll
    for (int f = 0; f < 4; f++)
        out[(size_t)row * DD + doff[f]] = res[f];
}

extern "C" void kernel_launch(void* const* d_in, const int* in_sizes, int n_in,
                              void* d_out, int out_size) {
    const float* x   = (const float*)d_in[0];
    const int*   adj = (const int*)d_in[1];
    float*       out = (float*)d_out;

    topk_kernel<<<DD, 1024>>>(x);
    probe_kernel<<<NN / 16, 512>>>(x, adj, out);
}

// round 11
// speedup vs baseline: 2.2240x; 1.0295x over previous
#include <cuda_runtime.h>
#include <math_constants.h>
#include <cfloat>

#define NN 8192
#define DD 128
#define TOPK 32

// Per-feature top-K, TRANSPOSED layout: g_topv[k*DD + d] = k-th largest of feature d.
__device__ __align__(16) float g_topv[TOPK * DD];
__device__ __align__(16) int   g_topi[TOPK * DD];

// Transposed x: xT[d][r] (4 MB static scratch).
__device__ __align__(16) float g_xT[DD * NN];

// float -> order-preserving uint32 (bijective; larger float => larger uint)
__device__ __forceinline__ unsigned f2ord(float f) {
    unsigned b = __float_as_uint(f);
    return (b & 0x80000000u) ? ~b : (b | 0x80000000u);
}
__device__ __forceinline__ float ord2f(unsigned u) {
    unsigned b = (u & 0x80000000u) ? (u ^ 0x80000000u) : ~u;
    return __uint_as_float(b);
}

// ---------------------------------------------------------------------------
// Kernel 0: coalesced 32x32 tiled transpose x[NN][DD] -> xT[DD][NN].
// Removes the 32x L2 amplification of topk's column-strided reads.
// ---------------------------------------------------------------------------
__global__ __launch_bounds__(256) void transpose_kernel(const float* __restrict__ x) {
    __shared__ float tile[32][33];
    const int c0 = blockIdx.x * 32;   // feature base
    const int r0 = blockIdx.y * 32;   // row base
    const int tx = threadIdx.x;
    const int ty = threadIdx.y;
#pragma unroll
    for (int i = 0; i < 32; i += 8)
        tile[ty + i][tx] = x[(size_t)(r0 + ty + i) * DD + c0 + tx];
    __syncthreads();
#pragma unroll
    for (int i = 0; i < 32; i += 8)
        g_xT[(size_t)(c0 + ty + i) * NN + r0 + tx] = tile[tx][ty + i];
}

// ---------------------------------------------------------------------------
// Kernel 1: per-feature top-K selection (R10-proven REDUX block argmax),
// now reading COALESCED from xT. One CTA (1024 threads) per feature d.
// ---------------------------------------------------------------------------
__global__ __launch_bounds__(1024) void topk_kernel() {
    const int d    = blockIdx.x;
    const int tid  = threadIdx.x;
    const int w    = tid >> 5;
    const int lane = tid & 31;

    const float* __restrict__ col = g_xT + (size_t)d * NN;

    unsigned v[8];
#pragma unroll
    for (int j = 0; j < 8; j++)
        v[j] = f2ord(col[j * 1024 + tid]);   // coalesced

    __shared__ unsigned s_wv[32];
    __shared__ int      s_wi[32];
    __shared__ int      s_bi;

    for (int k = 0; k < TOPK; k++) {
        // thread-local argmax over 8 register slots
        unsigned bk = v[0]; int bj = 0;
#pragma unroll
        for (int j = 1; j < 8; j++)
            if (v[j] > bk) { bk = v[j]; bj = j; }
        int bi = bj * 1024 + tid;  // global row index

        // warp argmax via REDUX + ballot (deterministic: lowest lane wins ties)
        unsigned wm   = __reduce_max_sync(0xffffffffu, bk);
        unsigned ball = __ballot_sync(0xffffffffu, bk == wm);
        int      src  = __ffs(ball) - 1;
        int      wbi  = __shfl_sync(0xffffffffu, bi, src);
        if (lane == 0) { s_wv[w] = wm; s_wi[w] = wbi; }
        __syncthreads();

        if (tid < 32) {
            unsigned k2 = s_wv[tid];
            int      i2 = s_wi[tid];
            unsigned wm2   = __reduce_max_sync(0xffffffffu, k2);
            unsigned ball2 = __ballot_sync(0xffffffffu, k2 == wm2);
            int      src2  = __ffs(ball2) - 1;
            int      wbi2  = __shfl_sync(0xffffffffu, i2, src2);
            if (tid == 0) {
                s_bi = wbi2;
                g_topv[k * DD + d] = ord2f(wm2);  // transposed table layout
                g_topi[k * DD + d] = wbi2;
            }
        }
        __syncthreads();

        // owner of the winning row clears its register slot (rows unique)
        int wi = s_bi;
        if ((wi & 1023) == tid) v[wi >> 10] = 0u;  // 0 < f2ord of any finite float
    }
}

// ---------------------------------------------------------------------------
// Kernel 2: probe (R3/R10-proven body, verbatim). One warp per row; lane owns
// 4 features (d = f*32+lane), advanced INTERLEAVED (MLP=4; probe k issued only
// after k-1 missed -> minimal DRAM bytes). Tables are [k][d] in gmem:
// float4-coalesced staging, bank-conflict-free LDS (bank = lane).
// ---------------------------------------------------------------------------
__global__ __launch_bounds__(512) void probe_kernel(const float* __restrict__ x,
                                                    const int*   __restrict__ adj,
                                                    float*       __restrict__ out) {
    __shared__ __align__(16) float s_topv[TOPK * DD];
    __shared__ __align__(16) int   s_topi[TOPK * DD];
    {
        const float4* gv = (const float4*)g_topv;
        const int4*   gi = (const int4*)g_topi;
        float4* sv = (float4*)s_topv;
        int4*   si = (int4*)s_topi;
        for (int t = threadIdx.x; t < TOPK * DD / 4; t += blockDim.x) {
            sv[t] = gv[t];
            si[t] = gi[t];
        }
    }
    __syncthreads();

    const int warp = threadIdx.x >> 5;
    const int lane = threadIdx.x & 31;
    const int row  = blockIdx.x * 16 + warp;
    const int* __restrict__ arow = adj + (size_t)row * NN;

    int doff[4];
#pragma unroll
    for (int f = 0; f < 4; f++) doff[f] = f * 32 + lane;

    int      k[4]  = {0, 0, 0, 0};
    float    res[4];
    unsigned done = 0;
    unsigned fb   = 0;

#pragma unroll 1
    while (done != 0xFu) {
        int cc[4], a[4];
#pragma unroll
        for (int f = 0; f < 4; f++)
            if (!((done >> f) & 1))
                cc[f] = s_topi[k[f] * DD + doff[f]];
#pragma unroll
        for (int f = 0; f < 4; f++)
            if (!((done >> f) & 1))
                a[f] = arow[cc[f]];
#pragma unroll
        for (int f = 0; f < 4; f++) {
            if (!((done >> f) & 1)) {
                if (a[f] != 0) {
                    res[f] = s_topv[k[f] * DD + doff[f]];
                    done |= 1u << f;
                } else if (++k[f] == TOPK) {
                    fb   |= 1u << f;      // exact fallback (~never: p=2^-32)
                    done |= 1u << f;
                }
            }
        }
    }

    if (fb) {  // exact fallback: full masked row scan (also no-neighbor -> 0)
#pragma unroll 1
        for (int f = 0; f < 4; f++) {
            if ((fb >> f) & 1) {
                const int d = doff[f];
                float m = -FLT_MAX; int any = 0;
                for (int j = 0; j < NN; j++) {
                    if (arow[j] != 0) { any = 1; m = fmaxf(m, x[(size_t)j * DD + d]); }
                }
                res[f] = any ? m : 0.0f;
            }
        }
    }

#pragma unroll
    for (int f = 0; f < 4; f++)
        out[(size_t)row * DD + doff[f]] = res[f];
}

extern "C" void kernel_launch(void* const* d_in, const int* in_sizes, int n_in,
                              void* d_out, int out_size) {
    const float* x   = (const float*)d_in[0];
    const int*   adj = (const int*)d_in[1];
    float*       out = (float*)d_out;

    transpose_kernel<<<dim3(DD / 32, NN / 32), dim3(32, 8)>>>(x);
    topk_kernel<<<DD, 1024>>>();
    probe_kernel<<<NN / 16, 512>>>(x, adj, out);
}